// round 11
// baseline (speedup 1.0000x reference)
#include <cuda_runtime.h>
#include <cuda_bf16.h>
#include <cstdint>

#define NMAX 50000
#define EMAX 1600000
#define HD   128

// ---------------- device scratch (static allocation, no cudaMalloc) ----------
__device__ int   g_deg[NMAX];
__device__ float g_dinv[NMAX];
__device__ int   g_rowptr[NMAX + 1];
__device__ int   g_fill[NMAX];
__device__ int   g_col[EMAX];
__device__ int   g_bsum[64];
__device__ float g_hs[(size_t)NMAX * HD];   // h = A @ W (gather source)
__device__ float g_h [(size_t)NMAX * HD];   // layer-1 output

// ---------------- degree ----------------------------------------------------
__global__ void k_deg_zero(int n) {
    int i = blockIdx.x * blockDim.x + threadIdx.x;
    if (i < n) g_deg[i] = 0;
}
__global__ void k_deg_count(const int* __restrict__ dst, int e, int n) {
    int i = blockIdx.x * blockDim.x + threadIdx.x;
    if (i < e) {
        int d = dst[i];
        if ((unsigned)d < (unsigned)n) atomicAdd(&g_deg[d], 1);
    }
}

// ---------------- parallel exclusive scan of deg ----------------------------
__global__ __launch_bounds__(1024) void k_scan1(int n) {
    __shared__ int ss[1024];
    int tid = threadIdx.x;
    int i = blockIdx.x * 1024 + tid;
    int v = (i < n) ? g_deg[i] : 0;
    if (i < n) g_dinv[i] = rsqrtf((float)(v + 1));
    ss[tid] = v;
    __syncthreads();
#pragma unroll
    for (int off = 1; off < 1024; off <<= 1) {
        int t = (tid >= off) ? ss[tid - off] : 0;
        __syncthreads();
        ss[tid] += t;
        __syncthreads();
    }
    if (i < n) g_rowptr[i] = ss[tid] - v;
    if (tid == 1023) g_bsum[blockIdx.x] = ss[1023];
}
__global__ __launch_bounds__(1024) void k_scan3(int n) {
    __shared__ int off_s;
    if (threadIdx.x == 0) {
        int o = 0;
        for (int j = 0; j < (int)blockIdx.x; j++) o += g_bsum[j];
        off_s = o;
    }
    __syncthreads();
    int i = blockIdx.x * 1024 + threadIdx.x;
    if (i >= n) return;
    int rp = g_rowptr[i] + off_s;
    g_rowptr[i] = rp;
    g_fill[i] = rp;
    if (i == n - 1) g_rowptr[n] = rp + g_deg[i];
}
__global__ void k_fill(const int* __restrict__ src,
                       const int* __restrict__ dst, int e, int n) {
    int i = blockIdx.x * blockDim.x + threadIdx.x;
    if (i >= e) return;
    int d = dst[i];
    int s = src[i];
    if ((unsigned)d >= (unsigned)n || (unsigned)s >= (unsigned)n) return;
    int pos = atomicAdd(&g_fill[d], 1);
    if (pos < EMAX) g_col[pos] = s;
}

// ---------------- mma.sync GEMM: g_hs = A @ W  (M x 128 @ 128 x 128) --------
// bf16 hi/lo 3-term split (AhWh + AhWl + AlWh), fp32 register accumulators.
// Block tile 128x128, 8 warps (4 m x 2 n), each warp 32x64 via m16n8k16 mma.
// smem tiles per 64-wide K chunk, rows padded to 72 bf16 (144B) -> conflict-free.
#define GPAD 72
#define GROWB (GPAD * 2)           // 144 bytes per row
#define AH_OFF 0
#define AL_OFF (128 * GROWB)       // 18432
#define BH_OFF (2 * 128 * GROWB)   // 36864
#define BL_OFF (3 * 128 * GROWB)   // 55296
#define GSM_TOTAL (4 * 128 * GROWB)

__device__ __forceinline__ uint32_t lds32(const char* base, int row, int kb) {
    return *(const uint32_t*)(base + row * GROWB + kb * 2);
}
__device__ __forceinline__ void mma_bf16(float* c, uint32_t a0, uint32_t a1,
                                         uint32_t a2, uint32_t a3,
                                         uint32_t b0, uint32_t b1) {
    asm volatile(
        "mma.sync.aligned.m16n8k16.row.col.f32.bf16.bf16.f32 "
        "{%0,%1,%2,%3}, {%4,%5,%6,%7}, {%8,%9}, {%0,%1,%2,%3};"
        : "+f"(c[0]), "+f"(c[1]), "+f"(c[2]), "+f"(c[3])
        : "r"(a0), "r"(a1), "r"(a2), "r"(a3), "r"(b0), "r"(b1));
}

template <int SRC>
__global__ __launch_bounds__(256) void k_gemm_mma(const float* __restrict__ Ax,
                                                  const float* __restrict__ W, int M) {
    extern __shared__ char smem[];
    const float* __restrict__ A = (SRC == 0) ? Ax : g_h;
    int tid = threadIdx.x;
    int lane = tid & 31;
    int wid = tid >> 5;
    int warp_m = wid & 3;      // 4 m-warps x 32 rows
    int warp_n = wid >> 2;     // 2 n-warps x 64 cols
    int row0 = blockIdx.x * 128;
    int gid = lane >> 2;       // groupID 0..7
    int tig = lane & 3;        // thread-in-group

    float c[2][8][4];
#pragma unroll
    for (int mt = 0; mt < 2; mt++)
#pragma unroll
        for (int nt = 0; nt < 8; nt++)
#pragma unroll
            for (int j = 0; j < 4; j++) c[mt][nt][j] = 0.f;

    for (int chunk = 0; chunk < 2; chunk++) {
        int k0 = chunk * 64;
        if (chunk > 0) __syncthreads();   // prior mma done before overwrite
        // ---- A tile: 128 x 64 fp32 -> hi/lo bf16, [m][k] padded rows
#pragma unroll
        for (int l = 0; l < 8; l++) {
            int f = l * 256 + tid;        // 0..2047 float4s
            int row = f >> 4;             // 16 float4 per row
            int col = (f & 15) << 2;
            int grow = row0 + row;
            float4 v = make_float4(0.f, 0.f, 0.f, 0.f);
            if (grow < M) v = *(const float4*)&A[(size_t)grow * 128 + k0 + col];
            __nv_bfloat16 h0 = __float2bfloat16(v.x);
            __nv_bfloat16 h1 = __float2bfloat16(v.y);
            __nv_bfloat16 h2 = __float2bfloat16(v.z);
            __nv_bfloat16 h3 = __float2bfloat16(v.w);
            __nv_bfloat16 l0 = __float2bfloat16(v.x - __bfloat162float(h0));
            __nv_bfloat16 l1 = __float2bfloat16(v.y - __bfloat162float(h1));
            __nv_bfloat16 l2 = __float2bfloat16(v.z - __bfloat162float(h2));
            __nv_bfloat16 l3 = __float2bfloat16(v.w - __bfloat162float(h3));
            char* ph = smem + AH_OFF + row * GROWB + col * 2;
            char* pl = smem + AL_OFF + row * GROWB + col * 2;
            *(__nv_bfloat162*)(ph)     = __nv_bfloat162(h0, h1);
            *(__nv_bfloat162*)(ph + 4) = __nv_bfloat162(h2, h3);
            *(__nv_bfloat162*)(pl)     = __nv_bfloat162(l0, l1);
            *(__nv_bfloat162*)(pl + 4) = __nv_bfloat162(l2, l3);
        }
        // ---- B tile: W[k0+k][n] -> [n][k] transposed, hi/lo bf16
#pragma unroll
        for (int l = 0; l < 8; l++) {
            int f = l * 256 + tid;        // 0..2047 float4s
            int k = f >> 5;               // 32 float4 per W row
            int n0 = (f & 31) << 2;
            float4 v = *(const float4*)&W[(size_t)(k0 + k) * 128 + n0];
            float vv[4] = {v.x, v.y, v.z, v.w};
#pragma unroll
            for (int j = 0; j < 4; j++) {
                __nv_bfloat16 h = __float2bfloat16(vv[j]);
                __nv_bfloat16 lo = __float2bfloat16(vv[j] - __bfloat162float(h));
                *(__nv_bfloat16*)(smem + BH_OFF + (n0 + j) * GROWB + k * 2) = h;
                *(__nv_bfloat16*)(smem + BL_OFF + (n0 + j) * GROWB + k * 2) = lo;
            }
        }
        __syncthreads();
        // ---- 3 terms x 4 k16-steps
#pragma unroll
        for (int t = 0; t < 3; t++) {
            const char* Ab = smem + ((t == 2) ? AL_OFF : AH_OFF);
            const char* Bb = smem + ((t == 1) ? BL_OFF : BH_OFF);
#pragma unroll
            for (int kt = 0; kt < 4; kt++) {
                int kb = kt * 16 + 2 * tig;
                uint32_t a[2][4];
#pragma unroll
                for (int mt = 0; mt < 2; mt++) {
                    int mr = warp_m * 32 + mt * 16 + gid;
                    a[mt][0] = lds32(Ab, mr,     kb);
                    a[mt][1] = lds32(Ab, mr + 8, kb);
                    a[mt][2] = lds32(Ab, mr,     kb + 8);
                    a[mt][3] = lds32(Ab, mr + 8, kb + 8);
                }
#pragma unroll
                for (int nt = 0; nt < 8; nt++) {
                    int nn = warp_n * 64 + nt * 8 + gid;
                    uint32_t b0 = lds32(Bb, nn, kb);
                    uint32_t b1 = lds32(Bb, nn, kb + 8);
                    mma_bf16(c[0][nt], a[0][0], a[0][1], a[0][2], a[0][3], b0, b1);
                    mma_bf16(c[1][nt], a[1][0], a[1][1], a[1][2], a[1][3], b0, b1);
                }
            }
        }
    }
    // ---- epilogue: direct STG of C fragments
#pragma unroll
    for (int mt = 0; mt < 2; mt++) {
        int r0 = row0 + warp_m * 32 + mt * 16 + gid;
        int r1 = r0 + 8;
#pragma unroll
        for (int nt = 0; nt < 8; nt++) {
            int cg = warp_n * 64 + nt * 8 + 2 * tig;
            if (r0 < M) *(float2*)&g_hs[(size_t)r0 * 128 + cg] =
                make_float2(c[mt][nt][0], c[mt][nt][1]);
            if (r1 < M) *(float2*)&g_hs[(size_t)r1 * 128 + cg] =
                make_float2(c[mt][nt][2], c[mt][nt][3]);
        }
    }
}

// ---------------- aggregation: one warp per node, CSR gather, 8-deep MLP ----
__global__ __launch_bounds__(256) void k_agg(const float* __restrict__ bias, int n) {
    int node = (int)((blockIdx.x * blockDim.x + threadIdx.x) >> 5);
    int lane = threadIdx.x & 31;
    if (node >= n) return;
    const float4* __restrict__ hs4 = (const float4*)g_hs;
    float dn = g_dinv[node];
    float4 hv = hs4[(size_t)node * 32 + lane];
    float4 acc;
    acc.x = __fmul_rn(hv.x, dn);
    acc.y = __fmul_rn(hv.y, dn);
    acc.z = __fmul_rn(hv.z, dn);
    acc.w = __fmul_rn(hv.w, dn);
    int beg = __ldg(&g_rowptr[node]);
    int end = __ldg(&g_rowptr[node + 1]);
    int e = beg;
    for (; e + 8 <= end; e += 8) {
        int   s[8];
        float d[8];
        float4 v[8];
#pragma unroll
        for (int u = 0; u < 8; u++) s[u] = __ldg(&g_col[e + u]);
#pragma unroll
        for (int u = 0; u < 8; u++) d[u] = __ldg(&g_dinv[s[u]]);
#pragma unroll
        for (int u = 0; u < 8; u++) v[u] = __ldg(&hs4[(size_t)s[u] * 32 + lane]);
        float4 p0, p1;
        p0.x = (__fmul_rn(v[0].x, d[0]) + __fmul_rn(v[1].x, d[1])) + (__fmul_rn(v[2].x, d[2]) + __fmul_rn(v[3].x, d[3]));
        p0.y = (__fmul_rn(v[0].y, d[0]) + __fmul_rn(v[1].y, d[1])) + (__fmul_rn(v[2].y, d[2]) + __fmul_rn(v[3].y, d[3]));
        p0.z = (__fmul_rn(v[0].z, d[0]) + __fmul_rn(v[1].z, d[1])) + (__fmul_rn(v[2].z, d[2]) + __fmul_rn(v[3].z, d[3]));
        p0.w = (__fmul_rn(v[0].w, d[0]) + __fmul_rn(v[1].w, d[1])) + (__fmul_rn(v[2].w, d[2]) + __fmul_rn(v[3].w, d[3]));
        p1.x = (__fmul_rn(v[4].x, d[4]) + __fmul_rn(v[5].x, d[5])) + (__fmul_rn(v[6].x, d[6]) + __fmul_rn(v[7].x, d[7]));
        p1.y = (__fmul_rn(v[4].y, d[4]) + __fmul_rn(v[5].y, d[5])) + (__fmul_rn(v[6].y, d[6]) + __fmul_rn(v[7].y, d[7]));
        p1.z = (__fmul_rn(v[4].z, d[4]) + __fmul_rn(v[5].z, d[5])) + (__fmul_rn(v[6].z, d[6]) + __fmul_rn(v[7].z, d[7]));
        p1.w = (__fmul_rn(v[4].w, d[4]) + __fmul_rn(v[5].w, d[5])) + (__fmul_rn(v[6].w, d[6]) + __fmul_rn(v[7].w, d[7]));
        acc.x += p0.x + p1.x;
        acc.y += p0.y + p1.y;
        acc.z += p0.z + p1.z;
        acc.w += p0.w + p1.w;
    }
    for (; e < end; e++) {
        int s = __ldg(&g_col[e]);
        float ds = __ldg(&g_dinv[s]);
        float4 v = __ldg(&hs4[(size_t)s * 32 + lane]);
        acc.x += __fmul_rn(v.x, ds);
        acc.y += __fmul_rn(v.y, ds);
        acc.z += __fmul_rn(v.z, ds);
        acc.w += __fmul_rn(v.w, ds);
    }
    float4 bb = __ldg(&((const float4*)bias)[lane]);
    float4 o;
    o.x = fmaxf(fmaf(dn, acc.x, bb.x), 0.f);
    o.y = fmaxf(fmaf(dn, acc.y, bb.y), 0.f);
    o.z = fmaxf(fmaf(dn, acc.z, bb.z), 0.f);
    o.w = fmaxf(fmaf(dn, acc.w, bb.w), 0.f);
    ((float4*)g_h)[(size_t)node * 32 + lane] = o;
}

// ---------------- fused agg2 + classifier head ------------------------------
// h2 = relu(dinv*(gather) + b2);  out[node] = h2 @ Wc + bc  (warp butterfly)
__global__ __launch_bounds__(256) void k_agg_final(const float* __restrict__ bias,
                                                   const float* __restrict__ Wc,
                                                   const float* __restrict__ bc,
                                                   float* __restrict__ Out, int n) {
    __shared__ float Wcs[128 * 16];
    __shared__ float bcs[16];
    int tid = threadIdx.x;
    for (int i = tid; i < 128 * 16; i += 256) Wcs[i] = Wc[i];
    if (tid < 16) bcs[tid] = bc[tid];
    __syncthreads();
    int node = (int)((blockIdx.x * blockDim.x + tid) >> 5);
    int lane = tid & 31;
    if (node >= n) return;
    const float4* __restrict__ hs4 = (const float4*)g_hs;
    float dn = g_dinv[node];
    float4 hv = hs4[(size_t)node * 32 + lane];
    float4 acc;
    acc.x = __fmul_rn(hv.x, dn);
    acc.y = __fmul_rn(hv.y, dn);
    acc.z = __fmul_rn(hv.z, dn);
    acc.w = __fmul_rn(hv.w, dn);
    int beg = __ldg(&g_rowptr[node]);
    int end = __ldg(&g_rowptr[node + 1]);
    int e = beg;
    for (; e + 8 <= end; e += 8) {
        int   s[8];
        float d[8];
        float4 v[8];
#pragma unroll
        for (int u = 0; u < 8; u++) s[u] = __ldg(&g_col[e + u]);
#pragma unroll
        for (int u = 0; u < 8; u++) d[u] = __ldg(&g_dinv[s[u]]);
#pragma unroll
        for (int u = 0; u < 8; u++) v[u] = __ldg(&hs4[(size_t)s[u] * 32 + lane]);
        float4 p0, p1;
        p0.x = (__fmul_rn(v[0].x, d[0]) + __fmul_rn(v[1].x, d[1])) + (__fmul_rn(v[2].x, d[2]) + __fmul_rn(v[3].x, d[3]));
        p0.y = (__fmul_rn(v[0].y, d[0]) + __fmul_rn(v[1].y, d[1])) + (__fmul_rn(v[2].y, d[2]) + __fmul_rn(v[3].y, d[3]));
        p0.z = (__fmul_rn(v[0].z, d[0]) + __fmul_rn(v[1].z, d[1])) + (__fmul_rn(v[2].z, d[2]) + __fmul_rn(v[3].z, d[3]));
        p0.w = (__fmul_rn(v[0].w, d[0]) + __fmul_rn(v[1].w, d[1])) + (__fmul_rn(v[2].w, d[2]) + __fmul_rn(v[3].w, d[3]));
        p1.x = (__fmul_rn(v[4].x, d[4]) + __fmul_rn(v[5].x, d[5])) + (__fmul_rn(v[6].x, d[6]) + __fmul_rn(v[7].x, d[7]));
        p1.y = (__fmul_rn(v[4].y, d[4]) + __fmul_rn(v[5].y, d[5])) + (__fmul_rn(v[6].y, d[6]) + __fmul_rn(v[7].y, d[7]));
        p1.z = (__fmul_rn(v[4].z, d[4]) + __fmul_rn(v[5].z, d[5])) + (__fmul_rn(v[6].z, d[6]) + __fmul_rn(v[7].z, d[7]));
        p1.w = (__fmul_rn(v[4].w, d[4]) + __fmul_rn(v[5].w, d[5])) + (__fmul_rn(v[6].w, d[6]) + __fmul_rn(v[7].w, d[7]));
        acc.x += p0.x + p1.x;
        acc.y += p0.y + p1.y;
        acc.z += p0.z + p1.z;
        acc.w += p0.w + p1.w;
    }
    for (; e < end; e++) {
        int s = __ldg(&g_col[e]);
        float ds = __ldg(&g_dinv[s]);
        float4 v = __ldg(&hs4[(size_t)s * 32 + lane]);
        acc.x += __fmul_rn(v.x, ds);
        acc.y += __fmul_rn(v.y, ds);
        acc.z += __fmul_rn(v.z, ds);
        acc.w += __fmul_rn(v.w, ds);
    }
    float4 bb = __ldg(&((const float4*)bias)[lane]);
    float h2[4];
    h2[0] = fmaxf(fmaf(dn, acc.x, bb.x), 0.f);
    h2[1] = fmaxf(fmaf(dn, acc.y, bb.y), 0.f);
    h2[2] = fmaxf(fmaf(dn, acc.z, bb.z), 0.f);
    h2[3] = fmaxf(fmaf(dn, acc.w, bb.w), 0.f);
    // head: partials over this lane's 4 k-values, then warp butterfly
    float p[16];
#pragma unroll
    for (int j = 0; j < 16; j++) p[j] = 0.f;
    int kbase = lane * 4;
#pragma unroll
    for (int t = 0; t < 4; t++) {
        float ht = h2[t];
        const float* wr = &Wcs[(kbase + t) * 16];
#pragma unroll
        for (int j4 = 0; j4 < 4; j4++) {
            float4 w = *(const float4*)&wr[j4 * 4];
            p[j4 * 4 + 0] += ht * w.x;
            p[j4 * 4 + 1] += ht * w.y;
            p[j4 * 4 + 2] += ht * w.z;
            p[j4 * 4 + 3] += ht * w.w;
        }
    }
#pragma unroll
    for (int off = 16; off >= 1; off >>= 1)
#pragma unroll
        for (int j = 0; j < 16; j++)
            p[j] += __shfl_xor_sync(0xffffffffu, p[j], off);
    if (lane < 4) {
        float4 ov;
        ov.x = p[lane * 4 + 0] + bcs[lane * 4 + 0];
        ov.y = p[lane * 4 + 1] + bcs[lane * 4 + 1];
        ov.z = p[lane * 4 + 2] + bcs[lane * 4 + 2];
        ov.w = p[lane * 4 + 3] + bcs[lane * 4 + 3];
        *(float4*)&Out[(size_t)node * 16 + lane * 4] = ov;
    }
}

// ---------------- launcher ---------------------------------------------------
extern "C" void kernel_launch(void* const* d_in, const int* in_sizes, int n_in,
                              void* d_out, int out_size) {
    const float* x  = (const float*)d_in[0];
    const int*   ei = (const int*)d_in[1];
    const float* W1 = (const float*)d_in[2];
    const float* b1 = (const float*)d_in[3];
    const float* W2 = (const float*)d_in[4];
    const float* b2 = (const float*)d_in[5];
    const float* Wc = (const float*)d_in[6];
    const float* bc = (const float*)d_in[7];
    float* out = (float*)d_out;

    int n = in_sizes[0] / HD;       // 50000
    int e = in_sizes[1] / 2;        // 1600000
    const int* srcp = ei;
    const int* dstp = ei + e;

    int gn256 = (n + 255) / 256;
    int ge256 = (e + 255) / 256;
    int nb = (n + 1023) / 1024;

    // one-time host-side setup (identical GPU work every call)
    static cudaStream_t s_side = (cudaStream_t)0;
    static cudaEvent_t  ev_fork = nullptr, ev_join = nullptr;
    static int s_init = 0;
    if (!s_init) {
        cudaStream_t st;
        cudaEvent_t e0, e1;
        if (cudaStreamCreateWithFlags(&st, cudaStreamNonBlocking) == cudaSuccess &&
            cudaEventCreateWithFlags(&e0, cudaEventDisableTiming) == cudaSuccess &&
            cudaEventCreateWithFlags(&e1, cudaEventDisableTiming) == cudaSuccess) {
            s_side = st; ev_fork = e0; ev_join = e1;
        }
        cudaFuncSetAttribute(k_gemm_mma<0>, cudaFuncAttributeMaxDynamicSharedMemorySize, GSM_TOTAL);
        cudaFuncSetAttribute(k_gemm_mma<1>, cudaFuncAttributeMaxDynamicSharedMemorySize, GSM_TOTAL);
        s_init = 1;
    }
    cudaStream_t sp = s_side;
    bool overlap = (s_side != (cudaStream_t)0);

    if (overlap) {
        cudaEventRecord(ev_fork, 0);
        cudaStreamWaitEvent(s_side, ev_fork, 0);
    }

    // CSR build on side stream (concurrent with gemm1)
    k_deg_zero<<<gn256, 256, 0, sp>>>(n);
    k_deg_count<<<ge256, 256, 0, sp>>>(dstp, e, n);
    k_scan1<<<nb, 1024, 0, sp>>>(n);
    k_scan3<<<nb, 1024, 0, sp>>>(n);
    k_fill<<<ge256, 256, 0, sp>>>(srcp, dstp, e, n);

    if (overlap) cudaEventRecord(ev_join, s_side);

    int gemm_blocks = (n + 127) / 128;
    int agg_blocks  = (n + 7) / 8;

    // layer 1
    k_gemm_mma<0><<<gemm_blocks, 256, GSM_TOTAL>>>(x, W1, n);
    if (overlap) cudaStreamWaitEvent(0, ev_join, 0);
    k_agg<<<agg_blocks, 256>>>(b1, n);
    // layer 2
    k_gemm_mma<1><<<gemm_blocks, 256, GSM_TOTAL>>>(x, W2, n);
    // fused agg2 + classifier head
    k_agg_final<<<agg_blocks, 256>>>(b2, Wc, bc, out, n);
}